// round 1
// baseline (speedup 1.0000x reference)
#include <cuda_runtime.h>
#include <cuda_bf16.h>
#include <cstdint>

// Problem constants
// B=32, N=512 -> M = 16384 frames
// D_MODEL=512, HEADS=8, DEPTH=147, dH=1176
#define M_ROWS   16384
#define DM       512
#define DH       1176
#define QKN      2352

// Scratch (device globals; no allocation APIs)
__device__ float g_QK[(size_t)M_ROWS * QKN];   // q | k  (154 MB)
__device__ float g_V [(size_t)M_ROWS * DH];    // v, attention written in-place (77 MB)

// ---------------------------------------------------------------------------
// SGEMM: C[M,N] = A[M,K] @ B[K,N] (+bias). Row-major everything.
// 128x128 block tile, BK=8, 256 threads, 8x8 per-thread micro tile.
// Requirements: M % 128 == 0, K % 8 == 0, N % 4 == 0 (all hold here).
// ---------------------------------------------------------------------------
__global__ void __launch_bounds__(256) sgemm_kernel(
    const float* __restrict__ A, const float* __restrict__ B,
    float* __restrict__ C, int M, int N, int K,
    const float* __restrict__ bias)
{
    constexpr int BM = 128, BN = 128, BK = 8;
    __shared__ float As[BK][BM];
    __shared__ float Bs[BK][BN];

    const int tid = threadIdx.x;
    const int tx  = tid & 15;      // 0..15 -> 8 cols each
    const int ty  = tid >> 4;      // 0..15 -> 8 rows each
    const int rowBase = blockIdx.y * BM;
    const int colBase = blockIdx.x * BN;

    // A tile loads: 128 rows x 8 k = 1024 floats = 256 threads x float4
    const int aRow = tid >> 1;            // 0..127
    const int aK   = (tid & 1) * 4;       // 0 or 4
    // B tile loads: 8 rows x 128 cols = 1024 floats
    const int bRow = tid >> 5;            // 0..7
    const int bCol = (tid & 31) * 4;      // 0..124

    const float* Aptr = A + (size_t)(rowBase + aRow) * K + aK;
    const int colB = colBase + bCol;
    const bool bInBounds = (colB < N);    // N % 4 == 0 -> whole float4 in/out

    float acc[8][8];
    #pragma unroll
    for (int i = 0; i < 8; i++)
        #pragma unroll
        for (int j = 0; j < 8; j++) acc[i][j] = 0.f;

    for (int k0 = 0; k0 < K; k0 += BK) {
        float4 av = *reinterpret_cast<const float4*>(Aptr + k0);
        As[aK + 0][aRow] = av.x;
        As[aK + 1][aRow] = av.y;
        As[aK + 2][aRow] = av.z;
        As[aK + 3][aRow] = av.w;

        float4 bv = make_float4(0.f, 0.f, 0.f, 0.f);
        if (bInBounds)
            bv = *reinterpret_cast<const float4*>(B + (size_t)(k0 + bRow) * N + colB);
        *reinterpret_cast<float4*>(&Bs[bRow][bCol]) = bv;

        __syncthreads();

        #pragma unroll
        for (int kk = 0; kk < BK; kk++) {
            float a[8], b[8];
            #pragma unroll
            for (int i = 0; i < 8; i++) a[i] = As[kk][ty * 8 + i];
            #pragma unroll
            for (int j = 0; j < 8; j++) b[j] = Bs[kk][tx * 8 + j];
            #pragma unroll
            for (int i = 0; i < 8; i++)
                #pragma unroll
                for (int j = 0; j < 8; j++)
                    acc[i][j] += a[i] * b[j];
        }
        __syncthreads();
    }

    #pragma unroll
    for (int i = 0; i < 8; i++) {
        const int row = rowBase + ty * 8 + i;
        #pragma unroll
        for (int j = 0; j < 8; j += 4) {
            const int col = colBase + tx * 8 + j;
            if (col < N) {
                float4 v = make_float4(acc[i][j], acc[i][j+1], acc[i][j+2], acc[i][j+3]);
                if (bias) {
                    v.x += bias[col + 0];
                    v.y += bias[col + 1];
                    v.z += bias[col + 2];
                    v.w += bias[col + 3];
                }
                *reinterpret_cast<float4*>(C + (size_t)row * N + col) = v;
            }
        }
    }
}

// ---------------------------------------------------------------------------
// Per-frame tiny attention. One warp per (frame m, head h).
// q channels [h*147+3 .. h*147+146] of QK; k same offset + 1176.
// Writes the 144 attended channels back into g_V in place.
// ---------------------------------------------------------------------------
__global__ void __launch_bounds__(256) attn_kernel(
    const float* __restrict__ QK, float* __restrict__ V)
{
    __shared__ float sh_k[8][144];
    __shared__ float sh_v[8][144];

    const int w    = threadIdx.x >> 5;
    const int lane = threadIdx.x & 31;
    const int gw   = blockIdx.x * 8 + w;     // global warp id: 0 .. 131071
    const int m    = gw >> 3;
    const int h    = gw & 7;

    const float* qrow = QK + (size_t)m * QKN + h * 147 + 3;
    const float* krow = QK + (size_t)m * QKN + 1176 + h * 147 + 3;
    float*       vrow = V  + (size_t)m * DH  + h * 147 + 3;

    // cooperative load of k & v slices
    for (int i = lane; i < 144; i += 32) {
        sh_k[w][i] = krow[i];
        sh_v[w][i] = vrow[i];
    }
    __syncwarp();

    const int j = lane;   // joint index, lanes 0..23 active
    float p[24];
    if (j < 24) {
        float q[6];
        #pragma unroll
        for (int t = 0; t < 6; t++) q[t] = qrow[j * 6 + t];

        const float scale = 0.4082482904638631f;  // 1/sqrt(6)
        #pragma unroll
        for (int kk = 0; kk < 24; kk++) {
            float s = 0.f;
            #pragma unroll
            for (int t = 0; t < 6; t++) s += q[t] * sh_k[w][kk * 6 + t];
            p[kk] = s * scale;
        }
        // softmax over k
        float mx = p[0];
        #pragma unroll
        for (int kk = 1; kk < 24; kk++) mx = fmaxf(mx, p[kk]);
        float sum = 0.f;
        #pragma unroll
        for (int kk = 0; kk < 24; kk++) { p[kk] = expf(p[kk] - mx); sum += p[kk]; }
        const float inv = 1.f / sum;
        #pragma unroll
        for (int kk = 0; kk < 24; kk++) p[kk] *= inv;
    }

    // --- custom weighting ---
    // Row-0 chain (all elements live in lane 0's p[]):
    if (lane == 0) {
        p[6]  = (p[6]  + p[3])  * 0.5f;
        p[9]  = (p[9]  + p[6])  * 0.5f;
        p[12] = (p[12] + p[9])  * 0.5f;
        p[13] = (p[13] + p[9])  * 0.5f;
        p[14] = (p[14] + p[9])  * 0.5f;
        p[16] = (p[16] + p[13]) * 0.5f;
        p[17] = (p[17] + p[14]) * 0.5f;
        p[15] = (p[15] + p[12]) * 0.5f;
    }
    // Column-0 chain (p[r][0] lives in lane r's p[0]); sequential via shuffles:
    {
        float c0 = (j < 24) ? p[0] : 0.f;
        float t;
        t = __shfl_sync(0xffffffffu, c0, 3);  if (lane == 6)  c0 = (c0 + t) * 0.5f;
        t = __shfl_sync(0xffffffffu, c0, 6);  if (lane == 9)  c0 = (c0 + t) * 0.5f;
        t = __shfl_sync(0xffffffffu, c0, 9);  if (lane >= 12 && lane <= 14) c0 = (c0 + t) * 0.5f;
        t = __shfl_sync(0xffffffffu, c0, 13); if (lane == 16) c0 = (c0 + t) * 0.5f;
        t = __shfl_sync(0xffffffffu, c0, 14); if (lane == 17) c0 = (c0 + t) * 0.5f;
        t = __shfl_sync(0xffffffffu, c0, 12); if (lane == 15) c0 = (c0 + t) * 0.5f;
        if (j < 24) p[0] = c0;
    }

    // attn = probs @ va ; write back in place
    if (j < 24) {
        #pragma unroll
        for (int t6 = 0; t6 < 6; t6++) {
            float o = 0.f;
            #pragma unroll
            for (int kk = 0; kk < 24; kk++) o += p[kk] * sh_v[w][kk * 6 + t6];
            vrow[j * 6 + t6] = o;
        }
    }
}

// ---------------------------------------------------------------------------
extern "C" void kernel_launch(void* const* d_in, const int* in_sizes, int n_in,
                              void* d_out, int out_size)
{
    const float* query = (const float*)d_in[0];
    // d_in[1] = key  (unused by the reference computation)
    const float* value = (const float*)d_in[2];
    const float* qk_w  = (const float*)d_in[3];
    const float* v_w   = (const float*)d_in[4];
    const float* lin_w = (const float*)d_in[5];
    const float* lin_b = (const float*)d_in[6];
    float* out = (float*)d_out;

    void* p;
    cudaGetSymbolAddress(&p, g_QK);
    float* QK = (float*)p;
    cudaGetSymbolAddress(&p, g_V);
    float* V = (float*)p;

    dim3 blk(256);

    // 1) QK = query @ qk_w  [16384 x 2352]
    sgemm_kernel<<<dim3((QKN + 127) / 128, M_ROWS / 128), blk>>>(
        query, qk_w, QK, M_ROWS, QKN, DM, nullptr);

    // 2) V = value @ v_w  [16384 x 1176]
    sgemm_kernel<<<dim3((DH + 127) / 128, M_ROWS / 128), blk>>>(
        value, v_w, V, M_ROWS, DH, DM, nullptr);

    // 3) per-frame tiny attention, in-place into V
    attn_kernel<<<(M_ROWS * 8) / 8, 256>>>(QK, V);

    // 4) out = V @ lin_w + lin_b  [16384 x 512]
    sgemm_kernel<<<dim3(DM / 128, M_ROWS / 128), blk>>>(
        V, lin_w, out, M_ROWS, DM, DH, lin_b);
}

// round 3
// speedup vs baseline: 2.8613x; 2.8613x over previous
#include <cuda_runtime.h>
#include <cuda_bf16.h>
#include <cstdint>

// ---------------------------------------------------------------------------
// B=32, N=512 -> M=16384 frames; D_MODEL=512, HEADS=8, DEPTH=147, dH=1176.
// GEMM1: QK[16384,2352] = query @ qk_w           (K=512)
// GEMM2: V [16384,1184] = value @ v_w (1176+pad) (K=512)
// attn : per-(frame,head) 24x24 softmax-attn, in place into V
// GEMM3: out[16384,512] = V @ lin_w + b          (K=1184, pad-K = zeros)
// ---------------------------------------------------------------------------
#define M_ROWS  16384
#define DM      512
#define NQK     2352
#define DH_REAL 1176
#define DH_PAD  1184
#define NOUT    512

__device__ __align__(16) float g_QK[(size_t)M_ROWS * NQK];
__device__ __align__(16) float g_V [(size_t)M_ROWS * DH_PAD];

__device__ __forceinline__ uint32_t smem_u32(const void* p) {
    uint32_t a;
    asm("{ .reg .u64 t; cvta.to.shared.u64 t, %1; cvt.u32.u64 %0, t; }"
        : "=r"(a) : "l"(p));
    return a;
}
__device__ __forceinline__ uint32_t f2tf32(float v) {
    uint32_t r;
    asm("cvt.rna.tf32.f32 %0, %1;" : "=r"(r) : "f"(v));
    return r;
}

// ---------------------------------------------------------------------------
// TF32 mma.sync GEMM.  C[M,ldc] = A[M,K] @ B[K_B, N_real] (+bias).
// BM=BN=128, BK=32, 3-stage cp.async pipeline, 256 threads.
// A fully dense [M,K] (K % 32 == 0, rows % 128 == 0).
// B row-major with row stride N_real; rows >= K_B and cols >= N_real zfilled.
// Writes cols < N_write (N_write even).
// ---------------------------------------------------------------------------
#define AS_LD   36              // 32 + 4 pad
#define BS_LD   132             // 128 + 4 pad
#define STAGE_FLOATS (128 * AS_LD + 32 * BS_LD)   // 4608 + 4224 = 8832
#define GEMM_SMEM_BYTES (3 * STAGE_FLOATS * 4)    // 105984

__global__ void __launch_bounds__(256) tf32_gemm(
    const float* __restrict__ A, const float* __restrict__ B,
    float* __restrict__ C, const float* __restrict__ bias,
    int K, int K_B, int N_real, int N_write, int ldc)
{
    extern __shared__ float sm[];
    const int tid  = threadIdx.x;
    const int lane = tid & 31;
    const int wid  = tid >> 5;
    const int wm   = wid >> 2;          // 0..1  (M)
    const int wn   = wid & 3;           // 0..3  (N)
    const int rowBase = blockIdx.y * 128;
    const int colBase = blockIdx.x * 128;
    const int KT = K / 32;
    const int ldb = N_real;

    float acc[4][4][4];
    #pragma unroll
    for (int mi = 0; mi < 4; mi++)
        #pragma unroll
        for (int ni = 0; ni < 4; ni++)
            #pragma unroll
            for (int r = 0; r < 4; r++) acc[mi][ni][r] = 0.f;

    auto load_chunk = [&](int chunk, int stg) {
        float* As = sm + stg * STAGE_FLOATS;
        float* Bs = As + 128 * AS_LD;
        const int k0 = chunk * 32;
        // A tile: 128 rows x 32 k  (always in bounds)
        #pragma unroll
        for (int t = tid; t < 1024; t += 256) {
            const int r = t >> 3, c = t & 7;
            const uint32_t dst = smem_u32(As + r * AS_LD + c * 4);
            const float* src = A + (size_t)(rowBase + r) * K + k0 + c * 4;
            asm volatile("cp.async.cg.shared.global [%0], [%1], 16;"
                         :: "r"(dst), "l"(src) : "memory");
        }
        // B tile: 32 k-rows x 128 cols, zfill OOB
        #pragma unroll
        for (int t = tid; t < 1024; t += 256) {
            const int r = t >> 5, c = t & 31;
            const uint32_t dst = smem_u32(Bs + r * BS_LD + c * 4);
            const int gk = k0 + r;
            const int gc = colBase + c * 4;
            const float* src = B + (size_t)gk * ldb + gc;
            const int sz = (gk < K_B && gc < N_real) ? 16 : 0;
            asm volatile("cp.async.cg.shared.global [%0], [%1], 16, %2;"
                         :: "r"(dst), "l"(src), "r"(sz) : "memory");
        }
    };

    // Prologue: stages 0,1
    load_chunk(0, 0);
    asm volatile("cp.async.commit_group;" ::: "memory");
    load_chunk(1, 1);
    asm volatile("cp.async.commit_group;" ::: "memory");

    for (int i = 0; i < KT; i++) {
        // Issue next prefetch, then wait for chunk i
        if (i + 2 < KT) {
            load_chunk(i + 2, (i + 2) % 3);
            asm volatile("cp.async.commit_group;" ::: "memory");
            asm volatile("cp.async.wait_group 2;" ::: "memory");
        } else if (i + 1 < KT) {
            asm volatile("cp.async.wait_group 1;" ::: "memory");
        } else {
            asm volatile("cp.async.wait_group 0;" ::: "memory");
        }
        __syncthreads();

        const float* As = sm + (i % 3) * STAGE_FLOATS;
        const float* Bs = As + 128 * AS_LD;

        #pragma unroll
        for (int ks = 0; ks < 4; ks++) {
            const int kk = ks * 8 + (lane & 3);
            uint32_t af[4][4], bf[4][2];
            #pragma unroll
            for (int mi = 0; mi < 4; mi++) {
                const int r = wm * 64 + mi * 16 + (lane >> 2);
                af[mi][0] = f2tf32(As[r * AS_LD + kk]);
                af[mi][1] = f2tf32(As[(r + 8) * AS_LD + kk]);
                af[mi][2] = f2tf32(As[r * AS_LD + kk + 4]);
                af[mi][3] = f2tf32(As[(r + 8) * AS_LD + kk + 4]);
            }
            #pragma unroll
            for (int ni = 0; ni < 4; ni++) {
                const int cI = wn * 32 + ni * 8 + (lane >> 2);
                bf[ni][0] = f2tf32(Bs[kk * BS_LD + cI]);
                bf[ni][1] = f2tf32(Bs[(kk + 4) * BS_LD + cI]);
            }
            #pragma unroll
            for (int mi = 0; mi < 4; mi++)
                #pragma unroll
                for (int ni = 0; ni < 4; ni++) {
                    asm volatile(
                        "mma.sync.aligned.m16n8k8.row.col.f32.tf32.tf32.f32 "
                        "{%0,%1,%2,%3}, {%4,%5,%6,%7}, {%8,%9}, {%0,%1,%2,%3};"
                        : "+f"(acc[mi][ni][0]), "+f"(acc[mi][ni][1]),
                          "+f"(acc[mi][ni][2]), "+f"(acc[mi][ni][3])
                        : "r"(af[mi][0]), "r"(af[mi][1]),
                          "r"(af[mi][2]), "r"(af[mi][3]),
                          "r"(bf[ni][0]), "r"(bf[ni][1]));
                }
        }
        __syncthreads();
    }

    // Epilogue
    #pragma unroll
    for (int mi = 0; mi < 4; mi++) {
        const int row0 = rowBase + wm * 64 + mi * 16 + (lane >> 2);
        #pragma unroll
        for (int ni = 0; ni < 4; ni++) {
            const int col = colBase + wn * 32 + ni * 8 + (lane & 3) * 2;
            if (col < N_write) {
                float b0 = 0.f, b1 = 0.f;
                if (bias) { b0 = bias[col]; b1 = bias[col + 1]; }
                float2 v0 = make_float2(acc[mi][ni][0] + b0, acc[mi][ni][1] + b1);
                float2 v1 = make_float2(acc[mi][ni][2] + b0, acc[mi][ni][3] + b1);
                *reinterpret_cast<float2*>(C + (size_t)row0 * ldc + col) = v0;
                *reinterpret_cast<float2*>(C + (size_t)(row0 + 8) * ldc + col) = v1;
            }
        }
    }
}

// ---------------------------------------------------------------------------
// Per-frame tiny attention. One warp per (frame m, head h).
// ---------------------------------------------------------------------------
__global__ void __launch_bounds__(256) attn_kernel(
    const float* __restrict__ QK, float* __restrict__ V)
{
    __shared__ float sh_k[8][144];
    __shared__ float sh_v[8][144];

    const int w    = threadIdx.x >> 5;
    const int lane = threadIdx.x & 31;
    const int gw   = blockIdx.x * 8 + w;
    const int m    = gw >> 3;
    const int h    = gw & 7;

    const float* qrow = QK + (size_t)m * NQK + h * 147 + 3;
    const float* krow = QK + (size_t)m * NQK + 1176 + h * 147 + 3;
    float*       vrow = V  + (size_t)m * DH_PAD + h * 147 + 3;

    for (int i = lane; i < 144; i += 32) {
        sh_k[w][i] = krow[i];
        sh_v[w][i] = vrow[i];
    }
    __syncwarp();

    const int j = lane;
    float p[24];
    if (j < 24) {
        float q[6];
        #pragma unroll
        for (int t = 0; t < 6; t++) q[t] = qrow[j * 6 + t];
        const float scale = 0.4082482904638631f;  // 1/sqrt(6)
        #pragma unroll
        for (int kk = 0; kk < 24; kk++) {
            float s = 0.f;
            #pragma unroll
            for (int t = 0; t < 6; t++) s += q[t] * sh_k[w][kk * 6 + t];
            p[kk] = s * scale;
        }
        float mx = p[0];
        #pragma unroll
        for (int kk = 1; kk < 24; kk++) mx = fmaxf(mx, p[kk]);
        float sum = 0.f;
        #pragma unroll
        for (int kk = 0; kk < 24; kk++) { p[kk] = expf(p[kk] - mx); sum += p[kk]; }
        const float inv = 1.f / sum;
        #pragma unroll
        for (int kk = 0; kk < 24; kk++) p[kk] *= inv;
    }

    // Row-0 weighting chain (lane 0 owns row 0)
    if (lane == 0) {
        p[6]  = (p[6]  + p[3])  * 0.5f;
        p[9]  = (p[9]  + p[6])  * 0.5f;
        p[12] = (p[12] + p[9])  * 0.5f;
        p[13] = (p[13] + p[9])  * 0.5f;
        p[14] = (p[14] + p[9])  * 0.5f;
        p[16] = (p[16] + p[13]) * 0.5f;
        p[17] = (p[17] + p[14]) * 0.5f;
        p[15] = (p[15] + p[12]) * 0.5f;
    }
    // Column-0 chain via shuffles (lane r owns p[r][0])
    {
        float c0 = (j < 24) ? p[0] : 0.f;
        float t;
        t = __shfl_sync(0xffffffffu, c0, 3);  if (lane == 6)  c0 = (c0 + t) * 0.5f;
        t = __shfl_sync(0xffffffffu, c0, 6);  if (lane == 9)  c0 = (c0 + t) * 0.5f;
        t = __shfl_sync(0xffffffffu, c0, 9);  if (lane >= 12 && lane <= 14) c0 = (c0 + t) * 0.5f;
        t = __shfl_sync(0xffffffffu, c0, 13); if (lane == 16) c0 = (c0 + t) * 0.5f;
        t = __shfl_sync(0xffffffffu, c0, 14); if (lane == 17) c0 = (c0 + t) * 0.5f;
        t = __shfl_sync(0xffffffffu, c0, 12); if (lane == 15) c0 = (c0 + t) * 0.5f;
        if (j < 24) p[0] = c0;
    }

    if (j < 24) {
        #pragma unroll
        for (int t6 = 0; t6 < 6; t6++) {
            float o = 0.f;
            #pragma unroll
            for (int kk = 0; kk < 24; kk++) o += p[kk] * sh_v[w][kk * 6 + t6];
            vrow[j * 6 + t6] = o;
        }
    }
}

// ---------------------------------------------------------------------------
extern "C" void kernel_launch(void* const* d_in, const int* in_sizes, int n_in,
                              void* d_out, int out_size)
{
    const float* query = (const float*)d_in[0];
    // d_in[1] = key (unused by the reference computation)
    const float* value = (const float*)d_in[2];
    const float* qk_w  = (const float*)d_in[3];
    const float* v_w   = (const float*)d_in[4];
    const float* lin_w = (const float*)d_in[5];
    const float* lin_b = (const float*)d_in[6];
    float* out = (float*)d_out;

    void* p;
    cudaGetSymbolAddress(&p, g_QK); float* QK = (float*)p;
    cudaGetSymbolAddress(&p, g_V);  float* V  = (float*)p;

    cudaFuncSetAttribute(tf32_gemm, cudaFuncAttributeMaxDynamicSharedMemorySize,
                         GEMM_SMEM_BYTES);

    // 1) QK = query @ qk_w : [16384 x 2352], K=512  (grid 19 x 128)
    tf32_gemm<<<dim3((NQK + 127) / 128, M_ROWS / 128), 256, GEMM_SMEM_BYTES>>>(
        query, qk_w, QK, nullptr, DM, DM, NQK, NQK, NQK);

    // 2) V = value @ v_w : [16384 x 1184], K=512 (cols 1176..1183 = 0)
    tf32_gemm<<<dim3((DH_PAD + 127) / 128, M_ROWS / 128), 256, GEMM_SMEM_BYTES>>>(
        value, v_w, V, nullptr, DM, DM, DH_REAL, DH_PAD, DH_PAD);

    // 3) per-frame tiny attention, in place into V
    attn_kernel<<<M_ROWS, 256>>>(QK, V);

    // 4) out = V @ lin_w + lin_b : [16384 x 512], K=1184 (pad rows zfilled)
    tf32_gemm<<<dim3(NOUT / 128, M_ROWS / 128), 256, GEMM_SMEM_BYTES>>>(
        V, lin_w, out, lin_b, DH_PAD, DH_REAL, NOUT, NOUT, NOUT);
}

// round 5
// speedup vs baseline: 2.9489x; 1.0306x over previous
#include <cuda_runtime.h>
#include <cuda_bf16.h>
#include <cstdint>

// ---------------------------------------------------------------------------
// B=32, N=512 -> M=16384 frames; D_MODEL=512, HEADS=8, DEPTH=147, dH=1176.
// Pipeline:
//   round(query)->g_Aq, round(value)->g_Av, round(weights)->g_*w (tf32 bits)
//   GEMM1: QK[16384,2352] = g_Aq @ qk_w_r          (K=512)
//   GEMM2: V [16384,1184] = g_Av @ v_w_r  (+pad)   (K=512)  [epilogue rounds]
//   attn : per-(frame,head) 24x24 softmax-attn in place into V [rounds]
//   GEMM3: out[16384,512] = V @ lin_w_r + b        (K=1184, pad-K zeros)
// ---------------------------------------------------------------------------
#define M_ROWS  16384
#define DM      512
#define NQK     2352
#define DH_REAL 1176
#define DH_PAD  1184
#define NOUT    512

__device__ __align__(16) float g_QK[(size_t)M_ROWS * NQK];
__device__ __align__(16) float g_V [(size_t)M_ROWS * DH_PAD];
__device__ __align__(16) float g_Aq[(size_t)M_ROWS * DM];
__device__ __align__(16) float g_Av[(size_t)M_ROWS * DM];
__device__ __align__(16) float g_qkw_r [(size_t)DM * NQK];
__device__ __align__(16) float g_vw_r  [(size_t)DM * DH_REAL];
__device__ __align__(16) float g_linw_r[(size_t)DH_REAL * NOUT];

__device__ __forceinline__ uint32_t smem_u32(const void* p) {
    uint32_t a;
    asm("{ .reg .u64 t; cvta.to.shared.u64 t, %1; cvt.u32.u64 %0, t; }"
        : "=r"(a) : "l"(p));
    return a;
}
__device__ __forceinline__ uint32_t f2tf32(float v) {
    uint32_t r;
    asm("cvt.rna.tf32.f32 %0, %1;" : "=r"(r) : "f"(v));
    return r;
}
__device__ __forceinline__ float roundtf(float v) {
    return __uint_as_float(f2tf32(v));
}

// ---------------------------------------------------------------------------
// Pre-round fp32 -> tf32-bit fp32 (low 13 mantissa bits zero), vectorized.
// ---------------------------------------------------------------------------
__global__ void __launch_bounds__(256) round_tf32_kernel(
    const float4* __restrict__ in, float4* __restrict__ out, int n4)
{
    int i = blockIdx.x * blockDim.x + threadIdx.x;
    if (i < n4) {
        float4 v = in[i];
        v.x = roundtf(v.x); v.y = roundtf(v.y);
        v.z = roundtf(v.z); v.w = roundtf(v.w);
        out[i] = v;
    }
}

// ---------------------------------------------------------------------------
// TF32 mma.sync GEMM (inputs pre-rounded; no cvt in mainloop).
// C[M,ldc] = A[M,K] @ B[K_B, N_real] (+bias). BM=BN=128, BK=32.
// 128 threads, 2x2 warp grid of 64x64 warp tiles, 3-stage cp.async.
// smem/CTA = 106KB -> 2 CTAs/SM.
// ---------------------------------------------------------------------------
#define AS_LD   36              // 32 + 4 pad
#define BS_LD   132             // 128 + 4 pad
#define STAGE_FLOATS (128 * AS_LD + 32 * BS_LD)   // 8832
#define GEMM_SMEM_BYTES (3 * STAGE_FLOATS * 4)    // 105984

__global__ void __launch_bounds__(128) tf32_gemm(
    const float* __restrict__ A, const float* __restrict__ B,
    float* __restrict__ C, const float* __restrict__ bias,
    int K, int K_B, int N_real, int N_write, int ldc, int round_out)
{
    extern __shared__ float sm[];
    const int tid  = threadIdx.x;
    const int lane = tid & 31;
    const int wid  = tid >> 5;
    const int wm   = wid >> 1;          // 0..1 -> 64-row half
    const int wn   = wid & 1;           // 0..1 -> 64-col half
    const int rowBase = blockIdx.y * 128;
    const int colBase = blockIdx.x * 128;
    const int KT = K / 32;
    const int ldb = N_real;

    float acc[4][8][4];
    #pragma unroll
    for (int mi = 0; mi < 4; mi++)
        #pragma unroll
        for (int ni = 0; ni < 8; ni++)
            #pragma unroll
            for (int r = 0; r < 4; r++) acc[mi][ni][r] = 0.f;

    auto load_chunk = [&](int chunk, int stg) {
        float* As = sm + stg * STAGE_FLOATS;
        float* Bs = As + 128 * AS_LD;
        const int k0 = chunk * 32;
        // A tile: 128 rows x 32 k (always in bounds)
        #pragma unroll
        for (int t = tid; t < 1024; t += 128) {
            const int r = t >> 3, c = t & 7;
            const uint32_t dst = smem_u32(As + r * AS_LD + c * 4);
            const float* src = A + (size_t)(rowBase + r) * K + k0 + c * 4;
            asm volatile("cp.async.cg.shared.global [%0], [%1], 16;"
                         :: "r"(dst), "l"(src) : "memory");
        }
        // B tile: 32 k-rows x 128 cols, zfill OOB
        #pragma unroll
        for (int t = tid; t < 1024; t += 128) {
            const int r = t >> 5, c = t & 31;
            const uint32_t dst = smem_u32(Bs + r * BS_LD + c * 4);
            const int gk = k0 + r;
            const int gc = colBase + c * 4;
            const float* src = B + (size_t)gk * ldb + gc;
            const int sz = (gk < K_B && gc < N_real) ? 16 : 0;
            asm volatile("cp.async.cg.shared.global [%0], [%1], 16, %2;"
                         :: "r"(dst), "l"(src), "r"(sz) : "memory");
        }
    };

    load_chunk(0, 0);
    asm volatile("cp.async.commit_group;" ::: "memory");
    load_chunk(1, 1);
    asm volatile("cp.async.commit_group;" ::: "memory");

    for (int i = 0; i < KT; i++) {
        if (i + 2 < KT) {
            load_chunk(i + 2, (i + 2) % 3);
            asm volatile("cp.async.commit_group;" ::: "memory");
            asm volatile("cp.async.wait_group 2;" ::: "memory");
        } else if (i + 1 < KT) {
            asm volatile("cp.async.wait_group 1;" ::: "memory");
        } else {
            asm volatile("cp.async.wait_group 0;" ::: "memory");
        }
        __syncthreads();

        const uint32_t* As = reinterpret_cast<const uint32_t*>(sm + (i % 3) * STAGE_FLOATS);
        const uint32_t* Bs = As + 128 * AS_LD;

        #pragma unroll
        for (int ks = 0; ks < 4; ks++) {
            const int kk = ks * 8 + (lane & 3);
            uint32_t af[4][4], bf[8][2];
            #pragma unroll
            for (int mi = 0; mi < 4; mi++) {
                const int r = wm * 64 + mi * 16 + (lane >> 2);
                af[mi][0] = As[r * AS_LD + kk];
                af[mi][1] = As[(r + 8) * AS_LD + kk];
                af[mi][2] = As[r * AS_LD + kk + 4];
                af[mi][3] = As[(r + 8) * AS_LD + kk + 4];
            }
            #pragma unroll
            for (int ni = 0; ni < 8; ni++) {
                const int cI = wn * 64 + ni * 8 + (lane >> 2);
                bf[ni][0] = Bs[kk * BS_LD + cI];
                bf[ni][1] = Bs[(kk + 4) * BS_LD + cI];
            }
            #pragma unroll
            for (int mi = 0; mi < 4; mi++)
                #pragma unroll
                for (int ni = 0; ni < 8; ni++) {
                    asm volatile(
                        "mma.sync.aligned.m16n8k8.row.col.f32.tf32.tf32.f32 "
                        "{%0,%1,%2,%3}, {%4,%5,%6,%7}, {%8,%9}, {%0,%1,%2,%3};"
                        : "+f"(acc[mi][ni][0]), "+f"(acc[mi][ni][1]),
                          "+f"(acc[mi][ni][2]), "+f"(acc[mi][ni][3])
                        : "r"(af[mi][0]), "r"(af[mi][1]),
                          "r"(af[mi][2]), "r"(af[mi][3]),
                          "r"(bf[ni][0]), "r"(bf[ni][1]));
                }
        }
        __syncthreads();
    }

    // Epilogue
    #pragma unroll
    for (int mi = 0; mi < 4; mi++) {
        const int row0 = rowBase + wm * 64 + mi * 16 + (lane >> 2);
        #pragma unroll
        for (int ni = 0; ni < 8; ni++) {
            const int col = colBase + wn * 64 + ni * 8 + (lane & 3) * 2;
            if (col < N_write) {
                float b0 = 0.f, b1 = 0.f;
                if (bias) { b0 = bias[col]; b1 = bias[col + 1]; }
                float v00 = acc[mi][ni][0] + b0, v01 = acc[mi][ni][1] + b1;
                float v10 = acc[mi][ni][2] + b0, v11 = acc[mi][ni][3] + b1;
                if (round_out) {
                    v00 = roundtf(v00); v01 = roundtf(v01);
                    v10 = roundtf(v10); v11 = roundtf(v11);
                }
                *reinterpret_cast<float2*>(C + (size_t)row0 * ldc + col) =
                    make_float2(v00, v01);
                *reinterpret_cast<float2*>(C + (size_t)(row0 + 8) * ldc + col) =
                    make_float2(v10, v11);
            }
        }
    }
}

// ---------------------------------------------------------------------------
// Per-frame tiny attention. One warp per (frame m, head h).
// Outputs written tf32-rounded (feeds GEMM3 with cvt-free mainloop).
// ---------------------------------------------------------------------------
__global__ void __launch_bounds__(256) attn_kernel(
    const float* __restrict__ QK, float* __restrict__ V)
{
    __shared__ float sh_k[8][144];
    __shared__ float sh_v[8][144];

    const int w    = threadIdx.x >> 5;
    const int lane = threadIdx.x & 31;
    const int gw   = blockIdx.x * 8 + w;
    const int m    = gw >> 3;
    const int h    = gw & 7;

    const float* qrow = QK + (size_t)m * NQK + h * 147 + 3;
    const float* krow = QK + (size_t)m * NQK + 1176 + h * 147 + 3;
    float*       vrow = V  + (size_t)m * DH_PAD + h * 147 + 3;

    for (int i = lane; i < 144; i += 32) {
        sh_k[w][i] = krow[i];
        sh_v[w][i] = vrow[i];
    }
    __syncwarp();

    const int j = lane;
    float p[24];
    if (j < 24) {
        float q[6];
        #pragma unroll
        for (int t = 0; t < 6; t++) q[t] = qrow[j * 6 + t];
        const float scale = 0.4082482904638631f;  // 1/sqrt(6)
        #pragma unroll
        for (int kk = 0; kk < 24; kk++) {
            float s = 0.f;
            #pragma unroll
            for (int t = 0; t < 6; t++) s += q[t] * sh_k[w][kk * 6 + t];
            p[kk] = s * scale;
        }
        float mx = p[0];
        #pragma unroll
        for (int kk = 1; kk < 24; kk++) mx = fmaxf(mx, p[kk]);
        float sum = 0.f;
        #pragma unroll
        for (int kk = 0; kk < 24; kk++) { p[kk] = expf(p[kk] - mx); sum += p[kk]; }
        const float inv = 1.f / sum;
        #pragma unroll
        for (int kk = 0; kk < 24; kk++) p[kk] *= inv;
    }

    // Row-0 weighting chain (lane 0 owns row 0)
    if (lane == 0) {
        p[6]  = (p[6]  + p[3])  * 0.5f;
        p[9]  = (p[9]  + p[6])  * 0.5f;
        p[12] = (p[12] + p[9])  * 0.5f;
        p[13] = (p[13] + p[9])  * 0.5f;
        p[14] = (p[14] + p[9])  * 0.5f;
        p[16] = (p[16] + p[13]) * 0.5f;
        p[17] = (p[17] + p[14]) * 0.5f;
        p[15] = (p[15] + p[12]) * 0.5f;
    }
    // Column-0 chain via shuffles (lane r owns p[r][0])
    {
        float c0 = (j < 24) ? p[0] : 0.f;
        float t;
        t = __shfl_sync(0xffffffffu, c0, 3);  if (lane == 6)  c0 = (c0 + t) * 0.5f;
        t = __shfl_sync(0xffffffffu, c0, 6);  if (lane == 9)  c0 = (c0 + t) * 0.5f;
        t = __shfl_sync(0xffffffffu, c0, 9);  if (lane >= 12 && lane <= 14) c0 = (c0 + t) * 0.5f;
        t = __shfl_sync(0xffffffffu, c0, 13); if (lane == 16) c0 = (c0 + t) * 0.5f;
        t = __shfl_sync(0xffffffffu, c0, 14); if (lane == 17) c0 = (c0 + t) * 0.5f;
        t = __shfl_sync(0xffffffffu, c0, 12); if (lane == 15) c0 = (c0 + t) * 0.5f;
        if (j < 24) p[0] = c0;
    }

    if (j < 24) {
        #pragma unroll
        for (int t6 = 0; t6 < 6; t6++) {
            float o = 0.f;
            #pragma unroll
            for (int kk = 0; kk < 24; kk++) o += p[kk] * sh_v[w][kk * 6 + t6];
            vrow[j * 6 + t6] = roundtf(o);
        }
    }
}

// ---------------------------------------------------------------------------
extern "C" void kernel_launch(void* const* d_in, const int* in_sizes, int n_in,
                              void* d_out, int out_size)
{
    const float* query = (const float*)d_in[0];
    // d_in[1] = key (unused by the reference computation)
    const float* value = (const float*)d_in[2];
    const float* qk_w  = (const float*)d_in[3];
    const float* v_w   = (const float*)d_in[4];
    const float* lin_w = (const float*)d_in[5];
    const float* lin_b = (const float*)d_in[6];
    float* out = (float*)d_out;

    void* p;
    cudaGetSymbolAddress(&p, g_QK);     float* QK     = (float*)p;
    cudaGetSymbolAddress(&p, g_V);      float* V      = (float*)p;
    cudaGetSymbolAddress(&p, g_Aq);     float* Aq     = (float*)p;
    cudaGetSymbolAddress(&p, g_Av);     float* Av     = (float*)p;
    cudaGetSymbolAddress(&p, g_qkw_r);  float* qkw_r  = (float*)p;
    cudaGetSymbolAddress(&p, g_vw_r);   float* vw_r   = (float*)p;
    cudaGetSymbolAddress(&p, g_linw_r); float* linw_r = (float*)p;

    cudaFuncSetAttribute(tf32_gemm, cudaFuncAttributeMaxDynamicSharedMemorySize,
                         GEMM_SMEM_BYTES);

    auto roundN = [&](const float* src, float* dst, size_t n) {
        int n4 = (int)(n / 4);
        round_tf32_kernel<<<(n4 + 255) / 256, 256>>>(
            (const float4*)src, (float4*)dst, n4);
    };
    roundN(query, Aq, (size_t)M_ROWS * DM);
    roundN(value, Av, (size_t)M_ROWS * DM);
    roundN(qk_w,  qkw_r,  (size_t)DM * NQK);
    roundN(v_w,   vw_r,   (size_t)DM * DH_REAL);
    roundN(lin_w, linw_r, (size_t)DH_REAL * NOUT);

    // 1) QK = query @ qk_w : [16384 x 2352], K=512
    tf32_gemm<<<dim3((NQK + 127) / 128, M_ROWS / 128), 128, GEMM_SMEM_BYTES>>>(
        Aq, qkw_r, QK, nullptr, DM, DM, NQK, NQK, NQK, 0);

    // 2) V = value @ v_w : [16384 x 1184], K=512 (cols 1176..1183 = 0), rounded out
    tf32_gemm<<<dim3((DH_PAD + 127) / 128, M_ROWS / 128), 128, GEMM_SMEM_BYTES>>>(
        Av, vw_r, V, nullptr, DM, DM, DH_REAL, DH_PAD, DH_PAD, 1);

    // 3) per-frame tiny attention, in place into V (rounded out)
    attn_kernel<<<M_ROWS, 256>>>(QK, V);

    // 4) out = V @ lin_w + lin_b : [16384 x 512], K=1184 (pad rows zfilled)
    tf32_gemm<<<dim3(NOUT / 128, M_ROWS / 128), 128, GEMM_SMEM_BYTES>>>(
        V, linw_r, out, lin_b, DH_PAD, DH_REAL, NOUT, NOUT, NOUT, 0);
}

// round 6
// speedup vs baseline: 5.3988x; 1.8308x over previous
#include <cuda_runtime.h>
#include <cuda_fp16.h>
#include <cstdint>

// ---------------------------------------------------------------------------
// B=32, N=512 -> M=16384 frames; D_MODEL=512, HEADS=8, DEPTH=147, dH=1176.
//   f2h: query,value,qk_w,v_w,lin_w -> fp16 scratch
//   GEMM1: QKh[16384,2352] = q_h @ qkw_h            (K=512)   fp16 out
//   GEMM2: Vh [16384,1280] = v_h @ vw_h (+pad)      (K=512)   fp16 out
//   attn : per-(frame,head) 24x24 softmax-attn in place into Vh
//   GEMM3: out[16384,512] = Vh @ linw_h + b         (K=1280, pad-K zeros)
// ---------------------------------------------------------------------------
#define M_ROWS  16384
#define DM      512
#define NQK     2352
#define DH_REAL 1176
#define DH_PAD  1280
#define NOUT    512

__device__ __align__(16) __half g_QKh [(size_t)M_ROWS * NQK];
__device__ __align__(16) __half g_Vh  [(size_t)M_ROWS * DH_PAD];
__device__ __align__(16) __half g_Aqh [(size_t)M_ROWS * DM];
__device__ __align__(16) __half g_Avh [(size_t)M_ROWS * DM];
__device__ __align__(16) __half g_qkwh[(size_t)DM * NQK];
__device__ __align__(16) __half g_vwh [(size_t)DM * DH_REAL];
__device__ __align__(16) __half g_linwh[(size_t)DH_REAL * NOUT];

__device__ __forceinline__ uint32_t smem_u32(const void* p) {
    uint32_t a;
    asm("{ .reg .u64 t; cvta.to.shared.u64 t, %1; cvt.u32.u64 %0, t; }"
        : "=r"(a) : "l"(p));
    return a;
}

// ---------------------------------------------------------------------------
// fp32 -> fp16 conversion, vectorized (n % 4 == 0).
// ---------------------------------------------------------------------------
__global__ void __launch_bounds__(256) f2h_kernel(
    const float4* __restrict__ in, uint2* __restrict__ out, int n4)
{
    int i = blockIdx.x * blockDim.x + threadIdx.x;
    if (i < n4) {
        float4 v = in[i];
        __half2 a = __floats2half2_rn(v.x, v.y);
        __half2 b = __floats2half2_rn(v.z, v.w);
        uint2 u;
        u.x = *reinterpret_cast<uint32_t*>(&a);
        u.y = *reinterpret_cast<uint32_t*>(&b);
        out[i] = u;
    }
}

// ---------------------------------------------------------------------------
// FP16 mma.sync GEMM with ldmatrix fragments.
// C[M,ldc] = A[M,K] @ B[K_B, N_real] (+bias). BM=BN=128, BK=64.
// 256 threads (2x4 warps, 64x32 warp tiles), 3-stage cp.async,
// 96KB smem -> 2 CTAs/SM (launch_bounds caps regs at 128).
// A smem tile: 128 rows x 128B (64 halves), swizzle off^((r&7)<<4).
// B smem tile:  64 rows x 256B (128 halves), swizzle off^((k&7)<<4).
// ---------------------------------------------------------------------------
#define STAGE_BYTES 32768
#define GEMM_SMEM_BYTES (3 * STAGE_BYTES)

#define LDSM_X4(r0,r1,r2,r3,addr) \
    asm volatile("ldmatrix.sync.aligned.m8n8.x4.shared.b16 {%0,%1,%2,%3}, [%4];" \
        : "=r"(r0), "=r"(r1), "=r"(r2), "=r"(r3) : "r"(addr))
#define LDSM_X4T(r0,r1,r2,r3,addr) \
    asm volatile("ldmatrix.sync.aligned.m8n8.x4.trans.shared.b16 {%0,%1,%2,%3}, [%4];" \
        : "=r"(r0), "=r"(r1), "=r"(r2), "=r"(r3) : "r"(addr))

template<bool OUT_HALF>
__global__ void __launch_bounds__(256, 2) h16_gemm(
    const __half* __restrict__ A, const __half* __restrict__ B,
    void* __restrict__ Cv, const float* __restrict__ bias,
    int K, int K_B, int N_real, int N_write, int ldc)
{
    extern __shared__ char smem[];
    const uint32_t sb = smem_u32(smem);
    const int tid  = threadIdx.x;
    const int lane = tid & 31;
    const int wid  = tid >> 5;
    const int wm   = wid >> 2;          // 0..1 -> 64-row half
    const int wn   = wid & 3;           // 0..3 -> 32-col quarter
    const int rowBase = blockIdx.y * 128;
    const int colBase = blockIdx.x * 128;
    const int KT = K / 64;

    float acc[4][4][4];
    #pragma unroll
    for (int mi = 0; mi < 4; mi++)
        #pragma unroll
        for (int ni = 0; ni < 4; ni++)
            #pragma unroll
            for (int r = 0; r < 4; r++) acc[mi][ni][r] = 0.f;

    auto load_chunk = [&](int chunk, int stg) {
        const int k0 = chunk * 64;
        const uint32_t ba = sb + stg * STAGE_BYTES;
        const uint32_t bb = ba + 16384;
        // A tile: 128 rows x 64 halves (always in bounds)
        #pragma unroll
        for (int idx = tid; idx < 1024; idx += 256) {
            const int r = idx >> 3, c = idx & 7;
            uint32_t off = (uint32_t)(r * 128 + c * 16);
            off ^= (uint32_t)((r & 7) << 4);
            const __half* src = A + (size_t)(rowBase + r) * K + k0 + c * 8;
            asm volatile("cp.async.cg.shared.global [%0], [%1], 16;"
                         :: "r"(ba + off), "l"(src) : "memory");
        }
        // B tile: 64 k-rows x 128 halves, zfill OOB
        #pragma unroll
        for (int idx = tid; idx < 1024; idx += 256) {
            const int k = idx >> 4, c = idx & 15;
            uint32_t off = (uint32_t)(k * 256 + c * 16);
            off ^= (uint32_t)((k & 7) << 4);
            const int gk = k0 + k;
            const int gc = colBase + c * 8;
            const __half* src = B + (size_t)gk * N_real + gc;
            const int sz = (gk < K_B && gc < N_real) ? 16 : 0;
            asm volatile("cp.async.cg.shared.global [%0], [%1], 16, %2;"
                         :: "r"(bb + off), "l"(src), "r"(sz) : "memory");
        }
    };

    load_chunk(0, 0);
    asm volatile("cp.async.commit_group;" ::: "memory");
    load_chunk(1, 1);
    asm volatile("cp.async.commit_group;" ::: "memory");

    const int lrow = lane & 15;
    const int lcol = (lane >> 4) << 3;
    const uint32_t xsw = (uint32_t)((lane & 7) << 4);

    for (int i = 0; i < KT; i++) {
        if (i + 2 < KT) {
            load_chunk(i + 2, (i + 2) % 3);
            asm volatile("cp.async.commit_group;" ::: "memory");
            asm volatile("cp.async.wait_group 2;" ::: "memory");
        } else if (i + 1 < KT) {
            asm volatile("cp.async.wait_group 1;" ::: "memory");
        } else {
            asm volatile("cp.async.wait_group 0;" ::: "memory");
        }
        __syncthreads();

        const uint32_t ba = sb + (i % 3) * STAGE_BYTES;
        const uint32_t bb = ba + 16384;

        #pragma unroll
        for (int ks = 0; ks < 4; ks++) {
            uint32_t af[4][4], bf[2][4];
            #pragma unroll
            for (int mi = 0; mi < 4; mi++) {
                const int row = wm * 64 + mi * 16 + lrow;
                const int col = ks * 16 + lcol;
                const uint32_t off = (uint32_t)(row * 128 + col * 2);
                LDSM_X4(af[mi][0], af[mi][1], af[mi][2], af[mi][3],
                        ba + (off ^ xsw));
            }
            #pragma unroll
            for (int nb = 0; nb < 2; nb++) {
                const int k = ks * 16 + lrow;
                const int n = wn * 32 + nb * 16 + lcol;
                const uint32_t off = (uint32_t)(k * 256 + n * 2);
                LDSM_X4T(bf[nb][0], bf[nb][1], bf[nb][2], bf[nb][3],
                         bb + (off ^ xsw));
            }
            #pragma unroll
            for (int mi = 0; mi < 4; mi++)
                #pragma unroll
                for (int ni = 0; ni < 4; ni++) {
                    const uint32_t b0 = bf[ni >> 1][(ni & 1) * 2];
                    const uint32_t b1 = bf[ni >> 1][(ni & 1) * 2 + 1];
                    asm volatile(
                        "mma.sync.aligned.m16n8k16.row.col.f32.f16.f16.f32 "
                        "{%0,%1,%2,%3}, {%4,%5,%6,%7}, {%8,%9}, {%0,%1,%2,%3};"
                        : "+f"(acc[mi][ni][0]), "+f"(acc[mi][ni][1]),
                          "+f"(acc[mi][ni][2]), "+f"(acc[mi][ni][3])
                        : "r"(af[mi][0]), "r"(af[mi][1]),
                          "r"(af[mi][2]), "r"(af[mi][3]),
                          "r"(b0), "r"(b1));
                }
        }
        __syncthreads();
    }

    // Epilogue
    const int erow  = wm * 64 + (lane >> 2);
    const int ecol0 = wn * 32 + (lane & 3) * 2;
    #pragma unroll
    for (int mi = 0; mi < 4; mi++) {
        const int row0 = rowBase + erow + mi * 16;
        #pragma unroll
        for (int ni = 0; ni < 4; ni++) {
            const int col = colBase + ecol0 + ni * 8;
            if (col < N_write) {
                if (OUT_HALF) {
                    __half* C = (__half*)Cv;
                    __half2 h0 = __floats2half2_rn(acc[mi][ni][0], acc[mi][ni][1]);
                    __half2 h1 = __floats2half2_rn(acc[mi][ni][2], acc[mi][ni][3]);
                    *reinterpret_cast<__half2*>(C + (size_t)row0 * ldc + col) = h0;
                    *reinterpret_cast<__half2*>(C + (size_t)(row0 + 8) * ldc + col) = h1;
                } else {
                    float* C = (float*)Cv;
                    float b0 = 0.f, b1 = 0.f;
                    if (bias) { b0 = bias[col]; b1 = bias[col + 1]; }
                    *reinterpret_cast<float2*>(C + (size_t)row0 * ldc + col) =
                        make_float2(acc[mi][ni][0] + b0, acc[mi][ni][1] + b1);
                    *reinterpret_cast<float2*>(C + (size_t)(row0 + 8) * ldc + col) =
                        make_float2(acc[mi][ni][2] + b0, acc[mi][ni][3] + b1);
                }
            }
        }
    }
}

// ---------------------------------------------------------------------------
// Per-frame tiny attention (fp16 in/out, fp32 math). One warp per (m, h).
// ---------------------------------------------------------------------------
__global__ void __launch_bounds__(256) attn_kernel(
    const __half* __restrict__ QK, __half* __restrict__ V)
{
    __shared__ float sh_k[8][144];
    __shared__ float sh_v[8][144];

    const int w    = threadIdx.x >> 5;
    const int lane = threadIdx.x & 31;
    const int gw   = blockIdx.x * 8 + w;
    const int m    = gw >> 3;
    const int h    = gw & 7;

    const __half* qrow = QK + (size_t)m * NQK + h * 147 + 3;
    const __half* krow = QK + (size_t)m * NQK + 1176 + h * 147 + 3;
    __half*       vrow = V  + (size_t)m * DH_PAD + h * 147 + 3;

    for (int i = lane; i < 144; i += 32) {
        sh_k[w][i] = __half2float(krow[i]);
        sh_v[w][i] = __half2float(vrow[i]);
    }
    __syncwarp();

    const int j = lane;
    float p[24];
    if (j < 24) {
        float q[6];
        #pragma unroll
        for (int t = 0; t < 6; t++) q[t] = __half2float(qrow[j * 6 + t]);
        const float scale = 0.4082482904638631f;  // 1/sqrt(6)
        #pragma unroll
        for (int kk = 0; kk < 24; kk++) {
            float s = 0.f;
            #pragma unroll
            for (int t = 0; t < 6; t++) s += q[t] * sh_k[w][kk * 6 + t];
            p[kk] = s * scale;
        }
        float mx = p[0];
        #pragma unroll
        for (int kk = 1; kk < 24; kk++) mx = fmaxf(mx, p[kk]);
        float sum = 0.f;
        #pragma unroll
        for (int kk = 0; kk < 24; kk++) { p[kk] = expf(p[kk] - mx); sum += p[kk]; }
        const float inv = 1.f / sum;
        #pragma unroll
        for (int kk = 0; kk < 24; kk++) p[kk] *= inv;
    }

    // Row-0 weighting chain (lane 0 owns row 0)
    if (lane == 0) {
        p[6]  = (p[6]  + p[3])  * 0.5f;
        p[9]  = (p[9]  + p[6])  * 0.5f;
        p[12] = (p[12] + p[9])  * 0.5f;
        p[13] = (p[13] + p[9])  * 0.5f;
        p[14] = (p[14] + p[9])  * 0.5f;
        p[16] = (p[16] + p[13]) * 0.5f;
        p[17] = (p[17] + p[14]) * 0.5f;
        p[15] = (p[15] + p[12]) * 0.5f;
    }
    // Column-0 chain via shuffles (lane r owns p[r][0])
    {
        float c0 = (j < 24) ? p[0] : 0.f;
        float t;
        t = __shfl_sync(0xffffffffu, c0, 3);  if (lane == 6)  c0 = (c0 + t) * 0.5f;
        t = __shfl_sync(0xffffffffu, c0, 6);  if (lane == 9)  c0 = (c0 + t) * 0.5f;
        t = __shfl_sync(0xffffffffu, c0, 9);  if (lane >= 12 && lane <= 14) c0 = (c0 + t) * 0.5f;
        t = __shfl_sync(0xffffffffu, c0, 13); if (lane == 16) c0 = (c0 + t) * 0.5f;
        t = __shfl_sync(0xffffffffu, c0, 14); if (lane == 17) c0 = (c0 + t) * 0.5f;
        t = __shfl_sync(0xffffffffu, c0, 12); if (lane == 15) c0 = (c0 + t) * 0.5f;
        if (j < 24) p[0] = c0;
    }

    if (j < 24) {
        #pragma unroll
        for (int t6 = 0; t6 < 6; t6++) {
            float o = 0.f;
            #pragma unroll
            for (int kk = 0; kk < 24; kk++) o += p[kk] * sh_v[w][kk * 6 + t6];
            vrow[j * 6 + t6] = __float2half_rn(o);
        }
    }
}

// ---------------------------------------------------------------------------
extern "C" void kernel_launch(void* const* d_in, const int* in_sizes, int n_in,
                              void* d_out, int out_size)
{
    const float* query = (const float*)d_in[0];
    // d_in[1] = key (unused by the reference computation)
    const float* value = (const float*)d_in[2];
    const float* qk_w  = (const float*)d_in[3];
    const float* v_w   = (const float*)d_in[4];
    const float* lin_w = (const float*)d_in[5];
    const float* lin_b = (const float*)d_in[6];
    float* out = (float*)d_out;

    void* p;
    cudaGetSymbolAddress(&p, g_QKh);   __half* QKh   = (__half*)p;
    cudaGetSymbolAddress(&p, g_Vh);    __half* Vh    = (__half*)p;
    cudaGetSymbolAddress(&p, g_Aqh);   __half* Aqh   = (__half*)p;
    cudaGetSymbolAddress(&p, g_Avh);   __half* Avh   = (__half*)p;
    cudaGetSymbolAddress(&p, g_qkwh);  __half* qkwh  = (__half*)p;
    cudaGetSymbolAddress(&p, g_vwh);   __half* vwh   = (__half*)p;
    cudaGetSymbolAddress(&p, g_linwh); __half* linwh = (__half*)p;

    cudaFuncSetAttribute(h16_gemm<true>,
        cudaFuncAttributeMaxDynamicSharedMemorySize, GEMM_SMEM_BYTES);
    cudaFuncSetAttribute(h16_gemm<false>,
        cudaFuncAttributeMaxDynamicSharedMemorySize, GEMM_SMEM_BYTES);

    auto conv = [&](const float* src, __half* dst, size_t n) {
        int n4 = (int)(n / 4);
        f2h_kernel<<<(n4 + 255) / 256, 256>>>(
            (const float4*)src, (uint2*)dst, n4);
    };
    conv(query, Aqh, (size_t)M_ROWS * DM);          // launch 0
    conv(value, Avh, (size_t)M_ROWS * DM);          // launch 1
    conv(qk_w,  qkwh, (size_t)DM * NQK);            // launch 2
    conv(v_w,   vwh,  (size_t)DM * DH_REAL);        // launch 3
    conv(lin_w, linwh, (size_t)DH_REAL * NOUT);     // launch 4

    // GEMM1 (launch 5 -> ncu -s 5 profiles this)
    h16_gemm<true><<<dim3((NQK + 127) / 128, M_ROWS / 128), 256, GEMM_SMEM_BYTES>>>(
        Aqh, qkwh, QKh, nullptr, DM, DM, NQK, NQK, NQK);

    // GEMM2: V fp16, pad cols 1176..1279 written as exact zeros
    h16_gemm<true><<<dim3(DH_PAD / 128, M_ROWS / 128), 256, GEMM_SMEM_BYTES>>>(
        Avh, vwh, Vh, nullptr, DM, DM, DH_REAL, DH_PAD, DH_PAD);

    // attn in place into Vh
    attn_kernel<<<M_ROWS, 256>>>(QKh, Vh);

    // GEMM3: fp32 out + bias; K=1280 (pad rows of lin_w zfilled)
    h16_gemm<false><<<dim3(NOUT / 128, M_ROWS / 128), 256, GEMM_SMEM_BYTES>>>(
        Vh, linwh, out, lin_b, DH_PAD, DH_REAL, NOUT, NOUT, NOUT);
}

// round 8
// speedup vs baseline: 5.5324x; 1.0247x over previous
#include <cuda_runtime.h>
#include <cuda_fp16.h>
#include <cstdint>

// ---------------------------------------------------------------------------
// B=32, N=512 -> M=16384 frames; D_MODEL=512, HEADS=8, DEPTH=147, dH=1176.
//   conv (1 launch): query,value,v_w,lin_w -> fp16
//   gather (1 launch): qk_w -> compacted fp16 [512 x 2304] (only used channels)
//   GEMM1: QKh[16384,2304] = q_h @ qkwc_h           (K=512)   fp16 out
//   GEMM2: Vh [16384,1216] = v_h @ vw_h (+pad)      (K=512)   fp16 out
//   attn : per-(frame,head) 24x24 softmax-attn in place into Vh
//   GEMM3: out[16384,512] = Vh @ linw_h + b         (K=1216, pad-K zeros)
// ---------------------------------------------------------------------------
#define M_ROWS  16384
#define DM      512
#define NQK_SRC 2352
#define NQKC    2304            // compacted: 2*8*144, 18 tiles of 128
#define DH_REAL 1176
#define DH_PAD  1216            // 19*64
#define NOUT    512

__device__ __align__(16) __half g_QKh [(size_t)M_ROWS * NQKC];
__device__ __align__(16) __half g_Vh  [(size_t)M_ROWS * DH_PAD];
__device__ __align__(16) __half g_Aqh [(size_t)M_ROWS * DM];
__device__ __align__(16) __half g_Avh [(size_t)M_ROWS * DM];
__device__ __align__(16) __half g_qkwc[(size_t)DM * NQKC];
__device__ __align__(16) __half g_vwh [(size_t)DM * DH_REAL];
__device__ __align__(16) __half g_linwh[(size_t)DH_REAL * NOUT];

__device__ __forceinline__ uint32_t smem_u32(const void* p) {
    uint32_t a;
    asm("{ .reg .u64 t; cvta.to.shared.u64 t, %1; cvt.u32.u64 %0, t; }"
        : "=r"(a) : "l"(p));
    return a;
}

// ---------------------------------------------------------------------------
// Fused fp32->fp16 conversion over 4 segments, grid-stride.
// ---------------------------------------------------------------------------
__global__ void __launch_bounds__(256) f2h_multi(
    const float4* __restrict__ s0, uint2* __restrict__ d0, int n0,
    const float4* __restrict__ s1, uint2* __restrict__ d1, int n1,
    const float4* __restrict__ s2, uint2* __restrict__ d2, int n2,
    const float4* __restrict__ s3, uint2* __restrict__ d3, int n3)
{
    const int total = n0 + n1 + n2 + n3;
    for (int i = blockIdx.x * blockDim.x + threadIdx.x; i < total;
         i += gridDim.x * blockDim.x) {
        const float4* s; uint2* d; int j = i;
        if (j < n0)                { s = s0; d = d0; }
        else if ((j -= n0) < n1)   { s = s1; d = d1; }
        else if ((j -= n1) < n2)   { s = s2; d = d2; }
        else { j -= n2;              s = s3; d = d3; }
        float4 v = s[j];
        __half2 a = __floats2half2_rn(v.x, v.y);
        __half2 b = __floats2half2_rn(v.z, v.w);
        uint2 u;
        u.x = *reinterpret_cast<uint32_t*>(&a);
        u.y = *reinterpret_cast<uint32_t*>(&b);
        d[j] = u;
    }
}

// ---------------------------------------------------------------------------
// qk_w gather-convert: [512 x 2352] fp32 -> compacted [512 x 2304] fp16.
// dst col c: part=c/1152, r=c%1152, head=r/144, ch=r%144
//            src col = part*1176 + head*147 + 3 + ch
// ---------------------------------------------------------------------------
__global__ void __launch_bounds__(256) gather_qkw(
    const float* __restrict__ src, __half* __restrict__ dst)
{
    const int n = DM * NQKC;
    for (int idx = blockIdx.x * blockDim.x + threadIdx.x; idx < n;
         idx += gridDim.x * blockDim.x) {
        const int row = idx / NQKC;
        const int c   = idx - row * NQKC;
        const int part = c / 1152;
        const int r    = c - part * 1152;
        const int head = r / 144;
        const int ch   = r - head * 144;
        const int sc   = part * 1176 + head * 147 + 3 + ch;
        dst[idx] = __float2half_rn(src[(size_t)row * NQK_SRC + sc]);
    }
}

// ---------------------------------------------------------------------------
// FP16 mma.sync GEMM with ldmatrix fragments.
// C[M,ldc] = A[M,K] @ B[K_B, N_real] (+bias). BM=BN=128, BK=64.
// 256 threads (2x4 warps, 64x32 warp tiles), 3-stage cp.async,
// 96KB smem -> 2 CTAs/SM.
// ---------------------------------------------------------------------------
#define STAGE_BYTES 32768
#define GEMM_SMEM_BYTES (3 * STAGE_BYTES)

#define LDSM_X4(r0,r1,r2,r3,addr) \
    asm volatile("ldmatrix.sync.aligned.m8n8.x4.shared.b16 {%0,%1,%2,%3}, [%4];" \
        : "=r"(r0), "=r"(r1), "=r"(r2), "=r"(r3) : "r"(addr))
#define LDSM_X4T(r0,r1,r2,r3,addr) \
    asm volatile("ldmatrix.sync.aligned.m8n8.x4.trans.shared.b16 {%0,%1,%2,%3}, [%4];" \
        : "=r"(r0), "=r"(r1), "=r"(r2), "=r"(r3) : "r"(addr))

template<bool OUT_HALF>
__global__ void __launch_bounds__(256, 2) h16_gemm(
    const __half* __restrict__ A, const __half* __restrict__ B,
    void* __restrict__ Cv, const float* __restrict__ bias,
    int K, int K_B, int N_real, int N_write, int ldc)
{
    extern __shared__ char smem[];
    const uint32_t sb = smem_u32(smem);
    const int tid  = threadIdx.x;
    const int lane = tid & 31;
    const int wid  = tid >> 5;
    const int wm   = wid >> 2;
    const int wn   = wid & 3;
    const int rowBase = blockIdx.y * 128;
    const int colBase = blockIdx.x * 128;
    const int KT = K / 64;

    float acc[4][4][4];
    #pragma unroll
    for (int mi = 0; mi < 4; mi++)
        #pragma unroll
        for (int ni = 0; ni < 4; ni++)
            #pragma unroll
            for (int r = 0; r < 4; r++) acc[mi][ni][r] = 0.f;

    auto load_chunk = [&](int chunk, int stg) {
        const int k0 = chunk * 64;
        const uint32_t ba = sb + stg * STAGE_BYTES;
        const uint32_t bb = ba + 16384;
        #pragma unroll
        for (int idx = tid; idx < 1024; idx += 256) {
            const int r = idx >> 3, c = idx & 7;
            uint32_t off = (uint32_t)(r * 128 + c * 16);
            off ^= (uint32_t)((r & 7) << 4);
            const __half* src = A + (size_t)(rowBase + r) * K + k0 + c * 8;
            asm volatile("cp.async.cg.shared.global [%0], [%1], 16;"
                         :: "r"(ba + off), "l"(src) : "memory");
        }
        #pragma unroll
        for (int idx = tid; idx < 1024; idx += 256) {
            const int k = idx >> 4, c = idx & 15;
            uint32_t off = (uint32_t)(k * 256 + c * 16);
            off ^= (uint32_t)((k & 7) << 4);
            const int gk = k0 + k;
            const int gc = colBase + c * 8;
            const __half* src = B + (size_t)gk * N_real + gc;
            const int sz = (gk < K_B && gc < N_real) ? 16 : 0;
            asm volatile("cp.async.cg.shared.global [%0], [%1], 16, %2;"
                         :: "r"(bb + off), "l"(src), "r"(sz) : "memory");
        }
    };

    load_chunk(0, 0);
    asm volatile("cp.async.commit_group;" ::: "memory");
    load_chunk(1, 1);
    asm volatile("cp.async.commit_group;" ::: "memory");

    const int lrow = lane & 15;
    const int lcol = (lane >> 4) << 3;
    const uint32_t xsw = (uint32_t)((lane & 7) << 4);

    for (int i = 0; i < KT; i++) {
        if (i + 2 < KT) {
            load_chunk(i + 2, (i + 2) % 3);
            asm volatile("cp.async.commit_group;" ::: "memory");
            asm volatile("cp.async.wait_group 2;" ::: "memory");
        } else if (i + 1 < KT) {
            asm volatile("cp.async.wait_group 1;" ::: "memory");
        } else {
            asm volatile("cp.async.wait_group 0;" ::: "memory");
        }
        __syncthreads();

        const uint32_t ba = sb + (i % 3) * STAGE_BYTES;
        const uint32_t bb = ba + 16384;

        #pragma unroll
        for (int ks = 0; ks < 4; ks++) {
            uint32_t af[4][4], bf[2][4];
            #pragma unroll
            for (int mi = 0; mi < 4; mi++) {
                const int row = wm * 64 + mi * 16 + lrow;
                const int col = ks * 16 + lcol;
                const uint32_t off = (uint32_t)(row * 128 + col * 2);
                LDSM_X4(af[mi][0], af[mi][1], af[mi][2], af[mi][3],
                        ba + (off ^ xsw));
            }
            #pragma unroll
            for (int nb = 0; nb < 2; nb++) {
                const int k = ks * 16 + lrow;
                const int n = wn * 32 + nb * 16 + lcol;
                const uint32_t off = (uint32_t)(k * 256 + n * 2);
                LDSM_X4T(bf[nb][0], bf[nb][1], bf[nb][2], bf[nb][3],
                         bb + (off ^ xsw));
            }
            #pragma unroll
            for (int mi = 0; mi < 4; mi++)
                #pragma unroll
                for (int ni = 0; ni < 4; ni++) {
                    const uint32_t b0 = bf[ni >> 1][(ni & 1) * 2];
                    const uint32_t b1 = bf[ni >> 1][(ni & 1) * 2 + 1];
                    asm volatile(
                        "mma.sync.aligned.m16n8k16.row.col.f32.f16.f16.f32 "
                        "{%0,%1,%2,%3}, {%4,%5,%6,%7}, {%8,%9}, {%0,%1,%2,%3};"
                        : "+f"(acc[mi][ni][0]), "+f"(acc[mi][ni][1]),
                          "+f"(acc[mi][ni][2]), "+f"(acc[mi][ni][3])
                        : "r"(af[mi][0]), "r"(af[mi][1]),
                          "r"(af[mi][2]), "r"(af[mi][3]),
                          "r"(b0), "r"(b1));
                }
        }
        __syncthreads();
    }

    const int erow  = wm * 64 + (lane >> 2);
    const int ecol0 = wn * 32 + (lane & 3) * 2;
    #pragma unroll
    for (int mi = 0; mi < 4; mi++) {
        const int row0 = rowBase + erow + mi * 16;
        #pragma unroll
        for (int ni = 0; ni < 4; ni++) {
            const int col = colBase + ecol0 + ni * 8;
            if (col < N_write) {
                if (OUT_HALF) {
                    __half* C = (__half*)Cv;
                    __half2 h0 = __floats2half2_rn(acc[mi][ni][0], acc[mi][ni][1]);
                    __half2 h1 = __floats2half2_rn(acc[mi][ni][2], acc[mi][ni][3]);
                    *reinterpret_cast<__half2*>(C + (size_t)row0 * ldc + col) = h0;
                    *reinterpret_cast<__half2*>(C + (size_t)(row0 + 8) * ldc + col) = h1;
                } else {
                    float* C = (float*)Cv;
                    float b0 = 0.f, b1 = 0.f;
                    if (bias) { b0 = bias[col]; b1 = bias[col + 1]; }
                    *reinterpret_cast<float2*>(C + (size_t)row0 * ldc + col) =
                        make_float2(acc[mi][ni][0] + b0, acc[mi][ni][1] + b1);
                    *reinterpret_cast<float2*>(C + (size_t)(row0 + 8) * ldc + col) =
                        make_float2(acc[mi][ni][2] + b0, acc[mi][ni][3] + b1);
                }
            }
        }
    }
}

// ---------------------------------------------------------------------------
// Per-frame tiny attention (fp16 in/out, fp32 math, fast exp).
// QK compacted: q at [m][h*144 + 0..143], k at +1152.
// ---------------------------------------------------------------------------
__global__ void __launch_bounds__(256) attn_kernel(
    const __half* __restrict__ QK, __half* __restrict__ V)
{
    __shared__ float sh_k[8][144];
    __shared__ float sh_v[8][144];

    const int w    = threadIdx.x >> 5;
    const int lane = threadIdx.x & 31;
    const int gw   = blockIdx.x * 8 + w;
    const int m    = gw >> 3;
    const int h    = gw & 7;

    const __half* qrow = QK + (size_t)m * NQKC + h * 144;
    const __half* krow = qrow + 1152;
    __half*       vrow = V  + (size_t)m * DH_PAD + h * 147 + 3;

    for (int i = lane; i < 144; i += 32) {
        sh_k[w][i] = __half2float(krow[i]);
        sh_v[w][i] = __half2float(vrow[i]);
    }
    __syncwarp();

    const int j = lane;
    float p[24];
    if (j < 24) {
        float q[6];
        #pragma unroll
        for (int t = 0; t < 6; t++) q[t] = __half2float(qrow[j * 6 + t]);
        const float scale = 0.4082482904638631f;  // 1/sqrt(6)
        #pragma unroll
        for (int kk = 0; kk < 24; kk++) {
            float s = 0.f;
            #pragma unroll
            for (int t = 0; t < 6; t++) s += q[t] * sh_k[w][kk * 6 + t];
            p[kk] = s * scale;
        }
        float mx = p[0];
        #pragma unroll
        for (int kk = 1; kk < 24; kk++) mx = fmaxf(mx, p[kk]);
        float sum = 0.f;
        #pragma unroll
        for (int kk = 0; kk < 24; kk++) { p[kk] = __expf(p[kk] - mx); sum += p[kk]; }
        const float inv = 1.f / sum;
        #pragma unroll
        for (int kk = 0; kk < 24; kk++) p[kk] *= inv;
    }

    if (lane == 0) {
        p[6]  = (p[6]  + p[3])  * 0.5f;
        p[9]  = (p[9]  + p[6])  * 0.5f;
        p[12] = (p[12] + p[9])  * 0.5f;
        p[13] = (p[13] + p[9])  * 0.5f;
        p[14] = (p[14] + p[9])  * 0.5f;
        p[16] = (p[16] + p[13]) * 0.5f;
        p[17] = (p[17] + p[14]) * 0.5f;
        p[15] = (p[15] + p[12]) * 0.5f;
    }
    {
        float c0 = (j < 24) ? p[0] : 0.f;
        float t;
        t = __shfl_sync(0xffffffffu, c0, 3);  if (lane == 6)  c0 = (c0 + t) * 0.5f;
        t = __shfl_sync(0xffffffffu, c0, 6);  if (lane == 9)  c0 = (c0 + t) * 0.5f;
        t = __shfl_sync(0xffffffffu, c0, 9);  if (lane >= 12 && lane <= 14) c0 = (c0 + t) * 0.5f;
        t = __shfl_sync(0xffffffffu, c0, 13); if (lane == 16) c0 = (c0 + t) * 0.5f;
        t = __shfl_sync(0xffffffffu, c0, 14); if (lane == 17) c0 = (c0 + t) * 0.5f;
        t = __shfl_sync(0xffffffffu, c0, 12); if (lane == 15) c0 = (c0 + t) * 0.5f;
        if (j < 24) p[0] = c0;
    }

    if (j < 24) {
        #pragma unroll
        for (int t6 = 0; t6 < 6; t6++) {
            float o = 0.f;
            #pragma unroll
            for (int kk = 0; kk < 24; kk++) o += p[kk] * sh_v[w][kk * 6 + t6];
            vrow[j * 6 + t6] = __float2half_rn(o);
        }
    }
}

// ---------------------------------------------------------------------------
extern "C" void kernel_launch(void* const* d_in, const int* in_sizes, int n_in,
                              void* d_out, int out_size)
{
    const float* query = (const float*)d_in[0];
    // d_in[1] = key (unused by the reference computation)
    const float* value = (const float*)d_in[2];
    const float* qk_w  = (const float*)d_in[3];
    const float* v_w   = (const float*)d_in[4];
    const float* lin_w = (const float*)d_in[5];
    const float* lin_b = (const float*)d_in[6];
    float* out = (float*)d_out;

    void* p;
    cudaGetSymbolAddress(&p, g_QKh);   __half* QKh   = (__half*)p;
    cudaGetSymbolAddress(&p, g_Vh);    __half* Vh    = (__half*)p;
    cudaGetSymbolAddress(&p, g_Aqh);   __half* Aqh   = (__half*)p;
    cudaGetSymbolAddress(&p, g_Avh);   __half* Avh   = (__half*)p;
    cudaGetSymbolAddress(&p, g_qkwc);  __half* qkwc  = (__half*)p;
    cudaGetSymbolAddress(&p, g_vwh);   __half* vwh   = (__half*)p;
    cudaGetSymbolAddress(&p, g_linwh); __half* linwh = (__half*)p;

    cudaFuncSetAttribute(h16_gemm<true>,
        cudaFuncAttributeMaxDynamicSharedMemorySize, GEMM_SMEM_BYTES);
    cudaFuncSetAttribute(h16_gemm<false>,
        cudaFuncAttributeMaxDynamicSharedMemorySize, GEMM_SMEM_BYTES);

    const int n0 = M_ROWS * DM / 4;          // query
    const int n1 = M_ROWS * DM / 4;          // value
    const int n2 = DM * DH_REAL / 4;         // v_w
    const int n3 = DH_REAL * NOUT / 4;       // lin_w
    const int total = n0 + n1 + n2 + n3;

    // launch 0: fused conversions
    f2h_multi<<<(total + 255) / 256, 256>>>(
        (const float4*)query, (uint2*)Aqh, n0,
        (const float4*)value, (uint2*)Avh, n1,
        (const float4*)v_w,   (uint2*)vwh, n2,
        (const float4*)lin_w, (uint2*)linwh, n3);

    // launch 1: qk_w gather-convert
    gather_qkw<<<(DM * NQKC + 255) / 256, 256>>>(qk_w, qkwc);

    // launch 2: GEMM1  QKh[16384,2304], K=512
    h16_gemm<true><<<dim3(NQKC / 128, M_ROWS / 128), 256, GEMM_SMEM_BYTES>>>(
        Aqh, qkwc, QKh, nullptr, DM, DM, NQKC, NQKC, NQKC);

    // launch 3: GEMM2  Vh[16384,1216], K=512 (cols 1176..1215 exact zeros)
    h16_gemm<true><<<dim3(1280 / 128, M_ROWS / 128), 256, GEMM_SMEM_BYTES>>>(
        Avh, vwh, Vh, nullptr, DM, DM, DH_REAL, DH_PAD, DH_PAD);

    // launch 4: attention in place into Vh
    attn_kernel<<<M_ROWS, 256>>>(QKh, Vh);

    // launch 5: GEMM3  out[16384,512], K=1216 (pad rows zfilled)  [ncu -s 5]
    h16_gemm<false><<<dim3(NOUT / 128, M_ROWS / 128), 256, GEMM_SMEM_BYTES>>>(
        Vh, linwh, out, lin_b, DH_PAD, DH_REAL, NOUT, NOUT, NOUT);
}

// round 9
// speedup vs baseline: 5.6205x; 1.0159x over previous
#include <cuda_runtime.h>
#include <cuda_fp16.h>
#include <cstdint>

// ---------------------------------------------------------------------------
// B=32, N=512 -> M=16384 frames; D_MODEL=512, HEADS=8, DEPTH=147, dH=1176.
//   conv (1 launch): query,value,v_w,lin_w -> fp16
//   gather (1 launch): qk_w -> compacted fp16 [512 x 2304]
//   GEMM1: QKh[16384,2304] = q_h @ qkwc_h           (K=512)   fp16 out
//   GEMM2: Vh [16384,1216] = v_h @ vw_h (+pad)      (K=512)   fp16 out
//   attn : per-(frame,head) 24x24 softmax-attn in place into Vh
//   GEMM3: out[16384,512] = Vh @ linw_h + b         (K=1216, pad-K zeros)
// GEMM CTA: 128 threads, 2x2 warps of 64x64 tiles (MMA:LDSM = 4.0).
// ---------------------------------------------------------------------------
#define M_ROWS  16384
#define DM      512
#define NQK_SRC 2352
#define NQKC    2304            // compacted: 2*8*144, 18 tiles of 128
#define DH_REAL 1176
#define DH_PAD  1216            // 19*64
#define NOUT    512

__device__ __align__(16) __half g_QKh [(size_t)M_ROWS * NQKC];
__device__ __align__(16) __half g_Vh  [(size_t)M_ROWS * DH_PAD];
__device__ __align__(16) __half g_Aqh [(size_t)M_ROWS * DM];
__device__ __align__(16) __half g_Avh [(size_t)M_ROWS * DM];
__device__ __align__(16) __half g_qkwc[(size_t)DM * NQKC];
__device__ __align__(16) __half g_vwh [(size_t)DM * DH_REAL];
__device__ __align__(16) __half g_linwh[(size_t)DH_REAL * NOUT];

__device__ __forceinline__ uint32_t smem_u32(const void* p) {
    uint32_t a;
    asm("{ .reg .u64 t; cvta.to.shared.u64 t, %1; cvt.u32.u64 %0, t; }"
        : "=r"(a) : "l"(p));
    return a;
}

// ---------------------------------------------------------------------------
// Fused fp32->fp16 conversion over 4 segments, grid-stride.
// ---------------------------------------------------------------------------
__global__ void __launch_bounds__(256) f2h_multi(
    const float4* __restrict__ s0, uint2* __restrict__ d0, int n0,
    const float4* __restrict__ s1, uint2* __restrict__ d1, int n1,
    const float4* __restrict__ s2, uint2* __restrict__ d2, int n2,
    const float4* __restrict__ s3, uint2* __restrict__ d3, int n3)
{
    const int total = n0 + n1 + n2 + n3;
    for (int i = blockIdx.x * blockDim.x + threadIdx.x; i < total;
         i += gridDim.x * blockDim.x) {
        const float4* s; uint2* d; int j = i;
        if (j < n0)                { s = s0; d = d0; }
        else if ((j -= n0) < n1)   { s = s1; d = d1; }
        else if ((j -= n1) < n2)   { s = s2; d = d2; }
        else { j -= n2;              s = s3; d = d3; }
        float4 v = s[j];
        __half2 a = __floats2half2_rn(v.x, v.y);
        __half2 b = __floats2half2_rn(v.z, v.w);
        uint2 u;
        u.x = *reinterpret_cast<uint32_t*>(&a);
        u.y = *reinterpret_cast<uint32_t*>(&b);
        d[j] = u;
    }
}

// ---------------------------------------------------------------------------
// qk_w gather-convert: [512 x 2352] fp32 -> compacted [512 x 2304] fp16.
// ---------------------------------------------------------------------------
__global__ void __launch_bounds__(256) gather_qkw(
    const float* __restrict__ src, __half* __restrict__ dst)
{
    const int n = DM * NQKC;
    for (int idx = blockIdx.x * blockDim.x + threadIdx.x; idx < n;
         idx += gridDim.x * blockDim.x) {
        const int row = idx / NQKC;
        const int c   = idx - row * NQKC;
        const int part = c / 1152;
        const int r    = c - part * 1152;
        const int head = r / 144;
        const int ch   = r - head * 144;
        const int sc   = part * 1176 + head * 147 + 3 + ch;
        dst[idx] = __float2half_rn(src[(size_t)row * NQK_SRC + sc]);
    }
}

// ---------------------------------------------------------------------------
// FP16 mma.sync GEMM with ldmatrix fragments.
// C[M,ldc] = A[M,K] @ B[K_B, N_real] (+bias). BM=BN=128, BK=64.
// 128 threads: 2x2 warp grid, 64x64 warp tiles. 3-stage cp.async, 96KB smem.
// ---------------------------------------------------------------------------
#define STAGE_BYTES 32768
#define GEMM_SMEM_BYTES (3 * STAGE_BYTES)

#define LDSM_X4(r0,r1,r2,r3,addr) \
    asm volatile("ldmatrix.sync.aligned.m8n8.x4.shared.b16 {%0,%1,%2,%3}, [%4];" \
        : "=r"(r0), "=r"(r1), "=r"(r2), "=r"(r3) : "r"(addr))
#define LDSM_X4T(r0,r1,r2,r3,addr) \
    asm volatile("ldmatrix.sync.aligned.m8n8.x4.trans.shared.b16 {%0,%1,%2,%3}, [%4];" \
        : "=r"(r0), "=r"(r1), "=r"(r2), "=r"(r3) : "r"(addr))

template<bool OUT_HALF>
__global__ void __launch_bounds__(128) h16_gemm(
    const __half* __restrict__ A, const __half* __restrict__ B,
    void* __restrict__ Cv, const float* __restrict__ bias,
    int K, int K_B, int N_real, int N_write, int ldc)
{
    extern __shared__ char smem[];
    const uint32_t sb = smem_u32(smem);
    const int tid  = threadIdx.x;
    const int lane = tid & 31;
    const int wid  = tid >> 5;
    const int wm   = wid >> 1;          // 0..1 -> 64-row half
    const int wn   = wid & 1;           // 0..1 -> 64-col half
    const int rowBase = blockIdx.y * 128;
    const int colBase = blockIdx.x * 128;
    const int KT = K / 64;

    float acc[4][8][4];
    #pragma unroll
    for (int mi = 0; mi < 4; mi++)
        #pragma unroll
        for (int ni = 0; ni < 8; ni++)
            #pragma unroll
            for (int r = 0; r < 4; r++) acc[mi][ni][r] = 0.f;

    auto load_chunk = [&](int chunk, int stg) {
        const int k0 = chunk * 64;
        const uint32_t ba = sb + stg * STAGE_BYTES;
        const uint32_t bb = ba + 16384;
        // A tile: 128 rows x 64 halves (always in bounds); 8 cp.async/thread
        #pragma unroll
        for (int idx = tid; idx < 1024; idx += 128) {
            const int r = idx >> 3, c = idx & 7;
            uint32_t off = (uint32_t)(r * 128 + c * 16);
            off ^= (uint32_t)((r & 7) << 4);
            const __half* src = A + (size_t)(rowBase + r) * K + k0 + c * 8;
            asm volatile("cp.async.cg.shared.global [%0], [%1], 16;"
                         :: "r"(ba + off), "l"(src) : "memory");
        }
        // B tile: 64 k-rows x 128 halves, zfill OOB; 8 cp.async/thread
        #pragma unroll
        for (int idx = tid; idx < 1024; idx += 128) {
            const int k = idx >> 4, c = idx & 15;
            uint32_t off = (uint32_t)(k * 256 + c * 16);
            off ^= (uint32_t)((k & 7) << 4);
            const int gk = k0 + k;
            const int gc = colBase + c * 8;
            const __half* src = B + (size_t)gk * N_real + gc;
            const int sz = (gk < K_B && gc < N_real) ? 16 : 0;
            asm volatile("cp.async.cg.shared.global [%0], [%1], 16, %2;"
                         :: "r"(bb + off), "l"(src), "r"(sz) : "memory");
        }
    };

    load_chunk(0, 0);
    asm volatile("cp.async.commit_group;" ::: "memory");
    load_chunk(1, 1);
    asm volatile("cp.async.commit_group;" ::: "memory");

    const int lrow = lane & 15;
    const int lcol = (lane >> 4) << 3;
    const uint32_t xsw = (uint32_t)((lane & 7) << 4);

    for (int i = 0; i < KT; i++) {
        if (i + 2 < KT) {
            load_chunk(i + 2, (i + 2) % 3);
            asm volatile("cp.async.commit_group;" ::: "memory");
            asm volatile("cp.async.wait_group 2;" ::: "memory");
        } else if (i + 1 < KT) {
            asm volatile("cp.async.wait_group 1;" ::: "memory");
        } else {
            asm volatile("cp.async.wait_group 0;" ::: "memory");
        }
        __syncthreads();

        const uint32_t ba = sb + (i % 3) * STAGE_BYTES;
        const uint32_t bb = ba + 16384;

        #pragma unroll
        for (int ks = 0; ks < 4; ks++) {
            uint32_t af[4][4], bf[4][4];
            #pragma unroll
            for (int mi = 0; mi < 4; mi++) {
                const int row = wm * 64 + mi * 16 + lrow;
                const int col = ks * 16 + lcol;
                const uint32_t off = (uint32_t)(row * 128 + col * 2);
                LDSM_X4(af[mi][0], af[mi][1], af[mi][2], af[mi][3],
                        ba + (off ^ xsw));
            }
            #pragma unroll
            for (int nb = 0; nb < 4; nb++) {
                const int k = ks * 16 + lrow;
                const int n = wn * 64 + nb * 16 + lcol;
                const uint32_t off = (uint32_t)(k * 256 + n * 2);
                LDSM_X4T(bf[nb][0], bf[nb][1], bf[nb][2], bf[nb][3],
                         bb + (off ^ xsw));
            }
            #pragma unroll
            for (int mi = 0; mi < 4; mi++)
                #pragma unroll
                for (int ni = 0; ni < 8; ni++) {
                    const uint32_t b0 = bf[ni >> 1][(ni & 1) * 2];
                    const uint32_t b1 = bf[ni >> 1][(ni & 1) * 2 + 1];
                    asm volatile(
                        "mma.sync.aligned.m16n8k16.row.col.f32.f16.f16.f32 "
                        "{%0,%1,%2,%3}, {%4,%5,%6,%7}, {%8,%9}, {%0,%1,%2,%3};"
                        : "+f"(acc[mi][ni][0]), "+f"(acc[mi][ni][1]),
                          "+f"(acc[mi][ni][2]), "+f"(acc[mi][ni][3])
                        : "r"(af[mi][0]), "r"(af[mi][1]),
                          "r"(af[mi][2]), "r"(af[mi][3]),
                          "r"(b0), "r"(b1));
                }
        }
        __syncthreads();
    }

    const int erow  = wm * 64 + (lane >> 2);
    const int ecol0 = wn * 64 + (lane & 3) * 2;
    #pragma unroll
    for (int mi = 0; mi < 4; mi++) {
        const int row0 = rowBase + erow + mi * 16;
        #pragma unroll
        for (int ni = 0; ni < 8; ni++) {
            const int col = colBase + ecol0 + ni * 8;
            if (col < N_write) {
                if (OUT_HALF) {
                    __half* C = (__half*)Cv;
                    __half2 h0 = __floats2half2_rn(acc[mi][ni][0], acc[mi][ni][1]);
                    __half2 h1 = __floats2half2_rn(acc[mi][ni][2], acc[mi][ni][3]);
                    *reinterpret_cast<__half2*>(C + (size_t)row0 * ldc + col) = h0;
                    *reinterpret_cast<__half2*>(C + (size_t)(row0 + 8) * ldc + col) = h1;
                } else {
                    float* C = (float*)Cv;
                    float b0 = 0.f, b1 = 0.f;
                    if (bias) { b0 = bias[col]; b1 = bias[col + 1]; }
                    *reinterpret_cast<float2*>(C + (size_t)row0 * ldc + col) =
                        make_float2(acc[mi][ni][0] + b0, acc[mi][ni][1] + b1);
                    *reinterpret_cast<float2*>(C + (size_t)(row0 + 8) * ldc + col) =
                        make_float2(acc[mi][ni][2] + b0, acc[mi][ni][3] + b1);
                }
            }
        }
    }
}

// ---------------------------------------------------------------------------
// Per-frame tiny attention (fp16 in/out, fp32 math, fast exp).
// QK compacted: q at [m][h*144 + 0..143], k at +1152.
// ---------------------------------------------------------------------------
__global__ void __launch_bounds__(256) attn_kernel(
    const __half* __restrict__ QK, __half* __restrict__ V)
{
    __shared__ float sh_k[8][144];
    __shared__ float sh_v[8][144];

    const int w    = threadIdx.x >> 5;
    const int lane = threadIdx.x & 31;
    const int gw   = blockIdx.x * 8 + w;
    const int m    = gw >> 3;
    const int h    = gw & 7;

    const __half* qrow = QK + (size_t)m * NQKC + h * 144;
    const __half* krow = qrow + 1152;
    __half*       vrow = V  + (size_t)m * DH_PAD + h * 147 + 3;

    for (int i = lane; i < 144; i += 32) {
        sh_k[w][i] = __half2float(krow[i]);
        sh_v[w][i] = __half2float(vrow[i]);
    }
    __syncwarp();

    const int j = lane;
    float p[24];
    if (j < 24) {
        float q[6];
        #pragma unroll
        for (int t = 0; t < 6; t++) q[t] = __half2float(qrow[j * 6 + t]);
        const float scale = 0.4082482904638631f;  // 1/sqrt(6)
        #pragma unroll
        for (int kk = 0; kk < 24; kk++) {
            float s = 0.f;
            #pragma unroll
            for (int t = 0; t < 6; t++) s += q[t] * sh_k[w][kk * 6 + t];
            p[kk] = s * scale;
        }
        float mx = p[0];
        #pragma unroll
        for (int kk = 1; kk < 24; kk++) mx = fmaxf(mx, p[kk]);
        float sum = 0.f;
        #pragma unroll
        for (int kk = 0; kk < 24; kk++) { p[kk] = __expf(p[kk] - mx); sum += p[kk]; }
        const float inv = 1.f / sum;
        #pragma unroll
        for (int kk = 0; kk < 24; kk++) p[kk] *= inv;
    }

    if (lane == 0) {
        p[6]  = (p[6]  + p[3])  * 0.5f;
        p[9]  = (p[9]  + p[6])  * 0.5f;
        p[12] = (p[12] + p[9])  * 0.5f;
        p[13] = (p[13] + p[9])  * 0.5f;
        p[14] = (p[14] + p[9])  * 0.5f;
        p[16] = (p[16] + p[13]) * 0.5f;
        p[17] = (p[17] + p[14]) * 0.5f;
        p[15] = (p[15] + p[12]) * 0.5f;
    }
    {
        float c0 = (j < 24) ? p[0] : 0.f;
        float t;
        t = __shfl_sync(0xffffffffu, c0, 3);  if (lane == 6)  c0 = (c0 + t) * 0.5f;
        t = __shfl_sync(0xffffffffu, c0, 6);  if (lane == 9)  c0 = (c0 + t) * 0.5f;
        t = __shfl_sync(0xffffffffu, c0, 9);  if (lane >= 12 && lane <= 14) c0 = (c0 + t) * 0.5f;
        t = __shfl_sync(0xffffffffu, c0, 13); if (lane == 16) c0 = (c0 + t) * 0.5f;
        t = __shfl_sync(0xffffffffu, c0, 14); if (lane == 17) c0 = (c0 + t) * 0.5f;
        t = __shfl_sync(0xffffffffu, c0, 12); if (lane == 15) c0 = (c0 + t) * 0.5f;
        if (j < 24) p[0] = c0;
    }

    if (j < 24) {
        #pragma unroll
        for (int t6 = 0; t6 < 6; t6++) {
            float o = 0.f;
            #pragma unroll
            for (int kk = 0; kk < 24; kk++) o += p[kk] * sh_v[w][kk * 6 + t6];
            vrow[j * 6 + t6] = __float2half_rn(o);
        }
    }
}

// ---------------------------------------------------------------------------
extern "C" void kernel_launch(void* const* d_in, const int* in_sizes, int n_in,
                              void* d_out, int out_size)
{
    const float* query = (const float*)d_in[0];
    // d_in[1] = key (unused by the reference computation)
    const float* value = (const float*)d_in[2];
    const float* qk_w  = (const float*)d_in[3];
    const float* v_w   = (const float*)d_in[4];
    const float* lin_w = (const float*)d_in[5];
    const float* lin_b = (const float*)d_in[6];
    float* out = (float*)d_out;

    void* p;
    cudaGetSymbolAddress(&p, g_QKh);   __half* QKh   = (__half*)p;
    cudaGetSymbolAddress(&p, g_Vh);    __half* Vh    = (__half*)p;
    cudaGetSymbolAddress(&p, g_Aqh);   __half* Aqh   = (__half*)p;
    cudaGetSymbolAddress(&p, g_Avh);   __half* Avh   = (__half*)p;
    cudaGetSymbolAddress(&p, g_qkwc);  __half* qkwc  = (__half*)p;
    cudaGetSymbolAddress(&p, g_vwh);   __half* vwh   = (__half*)p;
    cudaGetSymbolAddress(&p, g_linwh); __half* linwh = (__half*)p;

    cudaFuncSetAttribute(h16_gemm<true>,
        cudaFuncAttributeMaxDynamicSharedMemorySize, GEMM_SMEM_BYTES);
    cudaFuncSetAttribute(h16_gemm<false>,
        cudaFuncAttributeMaxDynamicSharedMemorySize, GEMM_SMEM_BYTES);

    const int n0 = M_ROWS * DM / 4;          // query
    const int n1 = M_ROWS * DM / 4;          // value
    const int n2 = DM * DH_REAL / 4;         // v_w
    const int n3 = DH_REAL * NOUT / 4;       // lin_w
    const int total = n0 + n1 + n2 + n3;

    // launch 0: fused conversions
    f2h_multi<<<(total + 255) / 256, 256>>>(
        (const float4*)query, (uint2*)Aqh, n0,
        (const float4*)value, (uint2*)Avh, n1,
        (const float4*)v_w,   (uint2*)vwh, n2,
        (const float4*)lin_w, (uint2*)linwh, n3);

    // launch 1: qk_w gather-convert
    gather_qkw<<<(DM * NQKC + 255) / 256, 256>>>(qk_w, qkwc);

    // launch 2: GEMM1  QKh[16384,2304], K=512
    h16_gemm<true><<<dim3(NQKC / 128, M_ROWS / 128), 128, GEMM_SMEM_BYTES>>>(
        Aqh, qkwc, QKh, nullptr, DM, DM, NQKC, NQKC, NQKC);

    // launch 3: GEMM2  Vh[16384,1216], K=512 (cols 1176..1215 exact zeros)
    h16_gemm<true><<<dim3(1280 / 128, M_ROWS / 128), 128, GEMM_SMEM_BYTES>>>(
        Avh, vwh, Vh, nullptr, DM, DM, DH_REAL, DH_PAD, DH_PAD);

    // launch 4: attention in place into Vh
    attn_kernel<<<M_ROWS, 256>>>(QKh, Vh);

    // launch 5: GEMM3  out[16384,512], K=1216 (pad rows zfilled)  [ncu -s 5]
    h16_gemm<false><<<dim3(NOUT / 128, M_ROWS / 128), 128, GEMM_SMEM_BYTES>>>(
        Vh, linwh, out, lin_b, DH_PAD, DH_REAL, NOUT, NOUT, NOUT);
}